// round 16
// baseline (speedup 1.0000x reference)
#include <cuda_runtime.h>
#include <cuda_fp16.h>

union U4 {
    uint4 u;
    __half2 h[4];
};

__global__ __launch_bounds__(256, 5) void slice_apply_kernel(
    const float* __restrict__ G,
    const float* __restrict__ guide,
    const float* __restrict__ fr,
    float* __restrict__ out)
{
    // Ta[sy(3)][z(8)][p(4)][xq(16)] 16B entries (ch0-7 fp16).
    //   bank16 = xq mod 8 -> phases of 8 consecutive quads are conflict-free,
    //   independent of per-lane z.
    // TbL/TbU[z(8)][p(4)][xq(16)] 16B: {syA ch8-11, syB ch8-11}, A,B=(0,1)/(1,2).
    __shared__ uint4 TaS[3 * 8 * 4 * 16];   // 24KB
    __shared__ uint4 TbL[8 * 4 * 16];       // 8KB
    __shared__ uint4 TbU[8 * 4 * 16];       // 8KB

    const int b   = blockIdx.z;
    const int tx  = blockIdx.x;        // x grid-cell (tile 64 px wide)
    const int by  = blockIdx.y;        // 64-row tile index (= y grid-cell)
    const int r0  = by << 6;
    const int tid = threadIdx.x;

    // ---- build: 384 jobs = (sy3, z8, xq16); each job writes p=0..3 entries.
    //      Reads the ORIGINAL grid layout G[b][c][z][y][x] directly (L2-resident,
    //      warp-broadcast) — no repack prepass. ----
    #pragma unroll
    for (int pass = 0; pass < 2; pass++) {
        if (pass == 1 && tid >= 128) break;
        const int j    = pass ? (256 + tid) : tid;
        const int xq   = j & 15;
        const int rest = j >> 4;           // 0..23
        const int z    = rest & 7;
        const int sy   = rest >> 3;        // 0..2
        const int half = xq >> 3;          // 0: xl<32 (fx0=tx-1), 1: xl>=32

        const int gy  = min(max(by - 1 + sy, 0), 15);
        const int gxa = half ? tx : max(tx - 1, 0);
        const int gxb = half ? min(tx + 1, 15) : tx;

        // G[b][c][z][gy][gx]: offset ((b*12+c)*8+z)*256 + gy*16 + gx
        const float* gbase = G + ((size_t)b * 12 * 8 * 256) + (size_t)z * 256 + (size_t)gy * 16;
        float s0[12], s1[12];
        #pragma unroll
        for (int c = 0; c < 12; c++) {
            s0[c] = __ldg(&gbase[c * 2048 + gxa]);
            s1[c] = __ldg(&gbase[c * 2048 + gxb]);
        }
        float dd[12];
        #pragma unroll
        for (int c = 0; c < 12; c++) dd[c] = s1[c] - s0[c];

        // wx = (xl+0.5)/64 + (half ? -0.5 : 0.5), xl = xq*4 + p
        const float wxb = ((float)(xq << 2) + 0.5f) * (1.0f / 64.0f) + (half ? -0.5f : 0.5f);

        #pragma unroll
        for (int p = 0; p < 4; p++) {
            const float wx = wxb + (float)p * (1.0f / 64.0f);
            float cc[12];
            #pragma unroll
            for (int c = 0; c < 12; c++) cc[c] = fmaf(wx, dd[c], s0[c]);

            U4 ta;
            ta.h[0] = __floats2half2_rn(cc[0], cc[1]);
            ta.h[1] = __floats2half2_rn(cc[2], cc[3]);
            ta.h[2] = __floats2half2_rn(cc[4], cc[5]);
            ta.h[3] = __floats2half2_rn(cc[6], cc[7]);
            TaS[(sy * 32 + z * 4 + p) * 16 + xq] = ta.u;

            const __half2 t89 = __floats2half2_rn(cc[8], cc[9]);
            const __half2 tAB = __floats2half2_rn(cc[10], cc[11]);
            const int e = (z * 4 + p) * 16 + xq;
            if (sy == 0) {
                __half2* q = (__half2*)&TbL[e];
                q[0] = t89; q[1] = tAB;
            } else if (sy == 1) {
                __half2* q = (__half2*)&TbL[e];
                q[2] = t89; q[3] = tAB;
                __half2* r = (__half2*)&TbU[e];
                r[0] = t89; r[1] = tAB;
            } else {
                __half2* r = (__half2*)&TbU[e];
                r[2] = t89; r[3] = tAB;
            }
        }
    }
    __syncthreads();

    // ---- main: lane = (r 0..3)*8 + qx(0..7). Phase = 8 consecutive quads on
    //      one row -> global LDG/STG hit full 128B lines; table LDS banks = xq
    //      mod 8 -> conflict-free regardless of z. ----
    const int lane = tid & 31;
    const int warp = tid >> 5;
    const int r    = lane >> 3;            // 0..3 row within group
    const int qx   = lane & 7;             // 0..7 quad within 32px half

    #pragma unroll 2
    for (int i = 0; i < 4; i++) {
        const int u      = warp + (i << 3);     // 0..31
        const int rowgrp = u >> 1;              // 0..15 (4 rows each)
        const int half   = u & 1;
        const int rr     = rowgrp >> 3;         // 0 lower / 1 upper 32 rows

        const int xqg = (half << 3) + qx;       // 0..15
        const int row = (rowgrp << 2) + r;
        const int y   = r0 + row;
        const int x   = (tx << 6) + (xqg << 2);

        // fy0 = by-1+rr for this half
        const float wy  = ((float)y + 0.5f) * (1.0f / 64.0f) - 0.5f - (float)(by - 1 + rr);
        const float wy0 = 1.0f - wy;

        const int  syOff = rr << 9;             // 0 or 512 (sy slot base in TaS)
        const uint4* Tb  = rr ? TbU : TbL;

        const size_t gBase  = (size_t)b * 1048576u + ((size_t)y << 10) + (size_t)x;
        const size_t frBase = (size_t)b * 3145728u + ((size_t)y << 10) + (size_t)x;

        const float4 g4  = __ldcs((const float4*)&guide[gBase]);
        const float4 fc0 = __ldcs((const float4*)&fr[frBase]);
        const float4 fc1 = __ldcs((const float4*)&fr[frBase + 1048576u]);
        const float4 fc2 = __ldcs((const float4*)&fr[frBase + 2097152u]);

        const float ga[4]  = {g4.x, g4.y, g4.z, g4.w};
        const float f0a[4] = {fc0.x, fc0.y, fc0.z, fc0.w};
        const float f1a[4] = {fc1.x, fc1.y, fc1.z, fc1.w};
        const float f2a[4] = {fc2.x, fc2.y, fc2.z, fc2.w};

        float o0[4], o1[4], o2[4];

        #pragma unroll
        for (int p = 0; p < 4; p++) {
            const float gz   = fmaf(ga[p], 8.0f, -0.5f);
            const float fz0f = floorf(gz);
            const float wz   = gz - fz0f;
            const int   fz0  = (int)fz0f;
            const int   z0   = max(fz0, 0);
            const int   z1   = min(fz0 + 1, 7);

            // fused (z,y) weights, one fp16 rounding stage total
            const float w00f = fmaf(-wy0, wz, wy0);   // (1-wz)(1-wy)
            const float w01f = wy0 * wz;              // wz(1-wy)
            const float w10f = fmaf(-wy, wz, wy);     // (1-wz)wy
            const float w11f = wy * wz;               // wz*wy
            const __half2 w00 = __float2half2_rn(w00f);
            const __half2 w01 = __float2half2_rn(w01f);
            const __half2 w10 = __float2half2_rn(w10f);
            const __half2 w11 = __float2half2_rn(w11f);

            const int e0 = (z0 * 4 + p) * 16 + xqg;
            const int e1 = (z1 * 4 + p) * 16 + xqg;

            U4 a00, a01, a10, a11, b0, b1;
            a00.u = TaS[syOff + e0];         // (z0, syA)
            a01.u = TaS[syOff + e1];         // (z1, syA)
            a10.u = TaS[syOff + 512 + e0];   // (z0, syB)
            a11.u = TaS[syOff + 512 + e1];   // (z1, syB)
            b0.u  = Tb[e0];
            b1.u  = Tb[e1];

            __half2 cy[4];
            #pragma unroll
            for (int k = 0; k < 4; k++) {
                __half2 t = __hmul2(w00, a00.h[k]);
                t = __hfma2(w01, a01.h[k], t);
                t = __hfma2(w10, a10.h[k], t);
                cy[k] = __hfma2(w11, a11.h[k], t);
            }
            const __half2 cb89 = __hfma2(w11, b1.h[2],
                                 __hfma2(w10, b0.h[2],
                                 __hfma2(w01, b1.h[0], __hmul2(w00, b0.h[0]))));
            const __half2 cbAB = __hfma2(w11, b1.h[3],
                                 __hfma2(w10, b0.h[3],
                                 __hfma2(w01, b1.h[1], __hmul2(w00, b0.h[1]))));

            const float2 c01 = __half22float2(cy[0]);
            const float2 c23 = __half22float2(cy[1]);
            const float2 c45 = __half22float2(cy[2]);
            const float2 c67 = __half22float2(cy[3]);
            const float2 c89 = __half22float2(cb89);
            const float2 cAB = __half22float2(cbAB);

            const float f0p = f0a[p], f1p = f1a[p], f2p = f2a[p];
            o0[p] = fmaf(c01.x, f0p, fmaf(c01.y, f1p, fmaf(c23.x, f2p, c23.y)));
            o1[p] = fmaf(c45.x, f0p, fmaf(c45.y, f1p, fmaf(c67.x, f2p, c67.y)));
            o2[p] = fmaf(c89.x, f0p, fmaf(c89.y, f1p, fmaf(cAB.x, f2p, cAB.y)));
        }

        __stcs((float4*)&out[frBase],            make_float4(o0[0], o0[1], o0[2], o0[3]));
        __stcs((float4*)&out[frBase + 1048576u], make_float4(o1[0], o1[1], o1[2], o1[3]));
        __stcs((float4*)&out[frBase + 2097152u], make_float4(o2[0], o2[1], o2[2], o2[3]));
    }
}

extern "C" void kernel_launch(void* const* d_in, const int* in_sizes, int n_in,
                              void* d_out, int out_size) {
    const float* G     = nullptr;
    const float* guide = nullptr;
    const float* fr    = nullptr;
    for (int i = 0; i < n_in; i++) {
        if (in_sizes[i] == 98304)          G     = (const float*)d_in[i];
        else if (in_sizes[i] == 4194304)   guide = (const float*)d_in[i];
        else if (in_sizes[i] == 12582912)  fr    = (const float*)d_in[i];
    }
    if (!G)     G     = (const float*)d_in[0];
    if (!guide) guide = (const float*)d_in[1];
    if (!fr)    fr    = (const float*)d_in[2];

    float* out = (float*)d_out;

    dim3 grid(16, 16, 4);   // x-tiles(64px), y-tiles(64rows), batch
    slice_apply_kernel<<<grid, 256>>>(G, guide, fr, out);
}

// round 17
// speedup vs baseline: 1.4257x; 1.4257x over previous
#include <cuda_runtime.h>
#include <cuda_fp16.h>

union U4 {
    uint4 u;
    __half2 h[4];
};

__global__ __launch_bounds__(256, 4) void slice_apply_kernel(
    const float* __restrict__ G,
    const float* __restrict__ guide,
    const float* __restrict__ fr,
    float* __restrict__ out)
{
    // Ta[sy(3)][z(8)][p(4)][xq(16)] 16B entries (ch0-7 fp16).
    //   bank16 = xq mod 8 -> phases of 8 consecutive quads are conflict-free,
    //   independent of per-lane z.
    // TbL/TbU[z(8)][p(4)][xq(16)] 16B: {syA ch8-11, syB ch8-11}, A,B=(0,1)/(1,2).
    __shared__ uint4 TaS[3 * 8 * 4 * 16];   // 24KB
    __shared__ uint4 TbL[8 * 4 * 16];       // 8KB
    __shared__ uint4 TbU[8 * 4 * 16];       // 8KB

    const int b   = blockIdx.z;
    const int tx  = blockIdx.x;        // x grid-cell (tile 64 px wide)
    const int by  = blockIdx.y;        // 64-row tile index (= y grid-cell)
    const int r0  = by << 6;
    const int tid = threadIdx.x;

    // ---- main-loop lane mapping (needed early for prefetch) ----
    const int lane = tid & 31;
    const int warp = tid >> 5;
    const int r    = lane >> 3;            // 0..3 row within group
    const int qx   = lane & 7;             // 0..7 quad within 32px half

    // Prefetch the 4 guide vectors before the barrier: independent of the
    // table, overlaps their DRAM latency with the build + sync.
    float4 g4v[4];
    int    yv[4];
    int    xqgv[4];
    size_t frBasev[4];
    #pragma unroll
    for (int i = 0; i < 4; i++) {
        const int u      = warp + (i << 3);     // 0..31
        const int rowgrp = u >> 1;              // 0..15 (4 rows each)
        const int half   = u & 1;
        const int xqg = (half << 3) + qx;       // 0..15
        const int row = (rowgrp << 2) + r;
        const int y   = r0 + row;
        const int x   = (tx << 6) + (xqg << 2);
        yv[i]   = y;
        xqgv[i] = xqg;
        const size_t gBase = (size_t)b * 1048576u + ((size_t)y << 10) + (size_t)x;
        frBasev[i] = (size_t)b * 3145728u + ((size_t)y << 10) + (size_t)x;
        g4v[i] = __ldcs((const float4*)&guide[gBase]);
    }

    // ---- build: 384 jobs = (sy3, z8, xq16); each job writes p=0..3 entries.
    //      Reads the ORIGINAL grid layout G[b][c][z][y][x] directly (L2-resident,
    //      warp-broadcast) — no repack prepass. ----
    #pragma unroll
    for (int pass = 0; pass < 2; pass++) {
        if (pass == 1 && tid >= 128) break;
        const int j    = pass ? (256 + tid) : tid;
        const int xq   = j & 15;
        const int rest = j >> 4;           // 0..23
        const int z    = rest & 7;
        const int sy   = rest >> 3;        // 0..2
        const int half = xq >> 3;          // 0: xl<32 (fx0=tx-1), 1: xl>=32

        const int gy  = min(max(by - 1 + sy, 0), 15);
        const int gxa = half ? tx : max(tx - 1, 0);
        const int gxb = half ? min(tx + 1, 15) : tx;

        // G[b][c][z][gy][gx]: offset ((b*12+c)*8+z)*256 + gy*16 + gx
        const float* gbase = G + ((size_t)b * 12 * 8 * 256) + (size_t)z * 256 + (size_t)gy * 16;
        float s0[12], s1[12];
        #pragma unroll
        for (int c = 0; c < 12; c++) {
            s0[c] = __ldg(&gbase[c * 2048 + gxa]);
            s1[c] = __ldg(&gbase[c * 2048 + gxb]);
        }
        float dd[12];
        #pragma unroll
        for (int c = 0; c < 12; c++) dd[c] = s1[c] - s0[c];

        // wx = (xl+0.5)/64 + (half ? -0.5 : 0.5), xl = xq*4 + p
        const float wxb = ((float)(xq << 2) + 0.5f) * (1.0f / 64.0f) + (half ? -0.5f : 0.5f);

        #pragma unroll
        for (int p = 0; p < 4; p++) {
            const float wx = wxb + (float)p * (1.0f / 64.0f);
            float cc[12];
            #pragma unroll
            for (int c = 0; c < 12; c++) cc[c] = fmaf(wx, dd[c], s0[c]);

            U4 ta;
            ta.h[0] = __floats2half2_rn(cc[0], cc[1]);
            ta.h[1] = __floats2half2_rn(cc[2], cc[3]);
            ta.h[2] = __floats2half2_rn(cc[4], cc[5]);
            ta.h[3] = __floats2half2_rn(cc[6], cc[7]);
            TaS[(sy * 32 + z * 4 + p) * 16 + xq] = ta.u;

            const __half2 t89 = __floats2half2_rn(cc[8], cc[9]);
            const __half2 tAB = __floats2half2_rn(cc[10], cc[11]);
            const int e = (z * 4 + p) * 16 + xq;
            if (sy == 0) {
                __half2* q = (__half2*)&TbL[e];
                q[0] = t89; q[1] = tAB;
            } else if (sy == 1) {
                __half2* q = (__half2*)&TbL[e];
                q[2] = t89; q[3] = tAB;
                __half2* rp = (__half2*)&TbU[e];
                rp[0] = t89; rp[1] = tAB;
            } else {
                __half2* rp = (__half2*)&TbU[e];
                rp[2] = t89; rp[3] = tAB;
            }
        }
    }
    __syncthreads();

    // ---- main: lane = (r 0..3)*8 + qx(0..7). Phase = 8 consecutive quads on
    //      one row -> global LDG/STG hit full 128B lines; table LDS banks = xq
    //      mod 8 -> conflict-free regardless of z. ----
    #pragma unroll
    for (int i = 0; i < 4; i++) {
        const int u      = warp + (i << 3);     // 0..31
        const int rowgrp = u >> 1;              // 0..15 (4 rows each)
        const int rr     = rowgrp >> 3;         // 0 lower / 1 upper 32 rows

        const int xqg = xqgv[i];
        const int y   = yv[i];

        // fy0 = by-1+rr for this half
        const float wy  = ((float)y + 0.5f) * (1.0f / 64.0f) - 0.5f - (float)(by - 1 + rr);
        const float wy0 = 1.0f - wy;

        const int  syOff = rr << 9;             // 0 or 512 (sy slot base in TaS)
        const uint4* Tb  = rr ? TbU : TbL;

        const size_t frBase = frBasev[i];

        const float4 fc0 = __ldcs((const float4*)&fr[frBase]);
        const float4 fc1 = __ldcs((const float4*)&fr[frBase + 1048576u]);
        const float4 fc2 = __ldcs((const float4*)&fr[frBase + 2097152u]);

        const float ga[4]  = {g4v[i].x, g4v[i].y, g4v[i].z, g4v[i].w};
        const float f0a[4] = {fc0.x, fc0.y, fc0.z, fc0.w};
        const float f1a[4] = {fc1.x, fc1.y, fc1.z, fc1.w};
        const float f2a[4] = {fc2.x, fc2.y, fc2.z, fc2.w};

        float o0[4], o1[4], o2[4];

        #pragma unroll
        for (int p = 0; p < 4; p++) {
            const float gz   = fmaf(ga[p], 8.0f, -0.5f);
            const float fz0f = floorf(gz);
            const float wz   = gz - fz0f;
            const int   fz0  = (int)fz0f;
            const int   z0   = max(fz0, 0);
            const int   z1   = min(fz0 + 1, 7);

            // fused (z,y) weights, one fp16 rounding stage total
            const float w00f = fmaf(-wy0, wz, wy0);   // (1-wz)(1-wy)
            const float w01f = wy0 * wz;              // wz(1-wy)
            const float w10f = fmaf(-wy, wz, wy);     // (1-wz)wy
            const float w11f = wy * wz;               // wz*wy
            const __half2 w00 = __float2half2_rn(w00f);
            const __half2 w01 = __float2half2_rn(w01f);
            const __half2 w10 = __float2half2_rn(w10f);
            const __half2 w11 = __float2half2_rn(w11f);

            const int e0 = (z0 * 4 + p) * 16 + xqg;
            const int e1 = (z1 * 4 + p) * 16 + xqg;

            U4 a00, a01, a10, a11, b0, b1;
            a00.u = TaS[syOff + e0];         // (z0, syA)
            a01.u = TaS[syOff + e1];         // (z1, syA)
            a10.u = TaS[syOff + 512 + e0];   // (z0, syB)
            a11.u = TaS[syOff + 512 + e1];   // (z1, syB)
            b0.u  = Tb[e0];
            b1.u  = Tb[e1];

            __half2 cy[4];
            #pragma unroll
            for (int k = 0; k < 4; k++) {
                __half2 t = __hmul2(w00, a00.h[k]);
                t = __hfma2(w01, a01.h[k], t);
                t = __hfma2(w10, a10.h[k], t);
                cy[k] = __hfma2(w11, a11.h[k], t);
            }
            const __half2 cb89 = __hfma2(w11, b1.h[2],
                                 __hfma2(w10, b0.h[2],
                                 __hfma2(w01, b1.h[0], __hmul2(w00, b0.h[0]))));
            const __half2 cbAB = __hfma2(w11, b1.h[3],
                                 __hfma2(w10, b0.h[3],
                                 __hfma2(w01, b1.h[1], __hmul2(w00, b0.h[1]))));

            const float2 c01 = __half22float2(cy[0]);
            const float2 c23 = __half22float2(cy[1]);
            const float2 c45 = __half22float2(cy[2]);
            const float2 c67 = __half22float2(cy[3]);
            const float2 c89 = __half22float2(cb89);
            const float2 cAB = __half22float2(cbAB);

            const float f0p = f0a[p], f1p = f1a[p], f2p = f2a[p];
            o0[p] = fmaf(c01.x, f0p, fmaf(c01.y, f1p, fmaf(c23.x, f2p, c23.y)));
            o1[p] = fmaf(c45.x, f0p, fmaf(c45.y, f1p, fmaf(c67.x, f2p, c67.y)));
            o2[p] = fmaf(c89.x, f0p, fmaf(c89.y, f1p, fmaf(cAB.x, f2p, cAB.y)));
        }

        __stcs((float4*)&out[frBase],            make_float4(o0[0], o0[1], o0[2], o0[3]));
        __stcs((float4*)&out[frBase + 1048576u], make_float4(o1[0], o1[1], o1[2], o1[3]));
        __stcs((float4*)&out[frBase + 2097152u], make_float4(o2[0], o2[1], o2[2], o2[3]));
    }
}

extern "C" void kernel_launch(void* const* d_in, const int* in_sizes, int n_in,
                              void* d_out, int out_size) {
    const float* G     = nullptr;
    const float* guide = nullptr;
    const float* fr    = nullptr;
    for (int i = 0; i < n_in; i++) {
        if (in_sizes[i] == 98304)          G     = (const float*)d_in[i];
        else if (in_sizes[i] == 4194304)   guide = (const float*)d_in[i];
        else if (in_sizes[i] == 12582912)  fr    = (const float*)d_in[i];
    }
    if (!G)     G     = (const float*)d_in[0];
    if (!guide) guide = (const float*)d_in[1];
    if (!fr)    fr    = (const float*)d_in[2];

    float* out = (float*)d_out;

    dim3 grid(16, 16, 4);   // x-tiles(64px), y-tiles(64rows), batch
    slice_apply_kernel<<<grid, 256>>>(G, guide, fr, out);
}